// round 2
// baseline (speedup 1.0000x reference)
#include <cuda_runtime.h>
#include <math.h>

#define NMAX 16384

// 128 MB scratch for stacked, stored block-transposed:
// stackedT[tile][k][r], tile = n/64, r = n%64, k = v*128 + o
__device__ __align__(256) float g_stackedT[(size_t)NMAX * 2048];

static __device__ __forceinline__ float eluf(float t) { return t > 0.f ? t : expm1f(t); }
static __device__ __forceinline__ float sigm(float t) { return 1.f / (1.f + expf(-t)); }

// ---------------------------------------------------------------------------
// Stage 1: per-variable GRN + LayerNorm -> g_stackedT
// grid = (N/64, 16), 256 threads. Block handles 64 rows x one variable.
// ---------------------------------------------------------------------------
__global__ void __launch_bounds__(256) vsn_stage1(
    const float* __restrict__ x,
    const float* __restrict__ W1, const float* __restrict__ b1,
    const float* __restrict__ W2, const float* __restrict__ b2,
    const float* __restrict__ Wg, const float* __restrict__ bg,
    const float* __restrict__ Ws, const float* __restrict__ bs,
    const float* __restrict__ gamma, const float* __restrict__ beta)
{
    extern __shared__ float sm[];
    float* sh_h  = sm;            // [128][68]  h transposed: [d][r]
    float* sh_w2 = sm + 8704;     // [64][132]
    float* sh_wg = sm + 17152;    // [64][132]
    float* sh_y  = sm + 25600;    // [64][133]
    float* sx    = sm + 34112;    // [64]
    float* smean = sm + 34176;    // [64]
    float* srstd = sm + 34240;    // [64]

    const int tid = threadIdx.x;
    const int rt = tid & 15;      // row-thread: rows rt*4 .. rt*4+3
    const int ot = tid >> 4;      // o-thread:  outputs ot*4 .. ot*4+3 (per chunk)
    const int v  = blockIdx.y;
    const int r0 = blockIdx.x * 64;

    for (int i = tid; i < 64; i += 256) sx[i] = x[(size_t)(r0 + i) * 16 + v];
    __syncthreads();

    // h[d][r] = elu(x[r]*W1[v,d] + b1[v,d])
    {
        const float* W1v = W1 + v * 128;
        const float* b1v = b1 + v * 128;
        for (int idx = tid; idx < 8192; idx += 256) {
            int r = idx & 63, d = idx >> 6;
            float t = fmaf(sx[r], W1v[d], b1v[d]);
            sh_h[d * 68 + r] = eluf(t);
        }
    }

    for (int oc = 0; oc < 128; oc += 64) {
        __syncthreads();   // previous chunk's W reads done / h ready
        // stage W2[v, oc..oc+63, :] and Wg chunk into shared
        const float* W2b = W2 + ((size_t)v * 128 + oc) * 128;
        const float* Wgb = Wg + ((size_t)v * 128 + oc) * 128;
        for (int idx = tid; idx < 2048; idx += 256) {
            int o = idx >> 5, dq = (idx & 31) * 4;
            float4 a = *(const float4*)(W2b + o * 128 + dq);
            float* p = sh_w2 + o * 132 + dq;
            p[0] = a.x; p[1] = a.y; p[2] = a.z; p[3] = a.w;
            float4 b = *(const float4*)(Wgb + o * 128 + dq);
            float* q = sh_wg + o * 132 + dq;
            q[0] = b.x; q[1] = b.y; q[2] = b.z; q[3] = b.w;
        }
        __syncthreads();

        float acc2[16], accg[16];
        #pragma unroll
        for (int t2 = 0; t2 < 16; t2++) { acc2[t2] = 0.f; accg[t2] = 0.f; }

        #pragma unroll 8
        for (int d = 0; d < 128; d++) {
            float4 hv = *(const float4*)(sh_h + d * 68 + rt * 4);
            #pragma unroll
            for (int i = 0; i < 4; i++) {
                float w2v = sh_w2[(ot * 4 + i) * 132 + d];
                float wgv = sh_wg[(ot * 4 + i) * 132 + d];
                acc2[0 * 4 + i] = fmaf(hv.x, w2v, acc2[0 * 4 + i]);
                acc2[1 * 4 + i] = fmaf(hv.y, w2v, acc2[1 * 4 + i]);
                acc2[2 * 4 + i] = fmaf(hv.z, w2v, acc2[2 * 4 + i]);
                acc2[3 * 4 + i] = fmaf(hv.w, w2v, acc2[3 * 4 + i]);
                accg[0 * 4 + i] = fmaf(hv.x, wgv, accg[0 * 4 + i]);
                accg[1 * 4 + i] = fmaf(hv.y, wgv, accg[1 * 4 + i]);
                accg[2 * 4 + i] = fmaf(hv.z, wgv, accg[2 * 4 + i]);
                accg[3 * 4 + i] = fmaf(hv.w, wgv, accg[3 * 4 + i]);
            }
        }

        // epilogue: y = g*h2 + (1-g)*skip into sh_y[r][o]
        #pragma unroll
        for (int i = 0; i < 4; i++) {
            int o = oc + ot * 4 + i;
            float b2v = b2[v * 128 + o];
            float bgv = bg[v * 128 + o];
            float wsv = Ws[v * 128 + o];
            float bsv = bs[v * 128 + o];
            #pragma unroll
            for (int j = 0; j < 4; j++) {
                int r = rt * 4 + j;
                float g  = sigm(accg[j * 4 + i] + bgv);
                float h2 = acc2[j * 4 + i] + b2v;
                float sk = fmaf(sx[r], wsv, bsv);
                sh_y[r * 133 + o] = g * h2 + (1.f - g) * sk;
            }
        }
    }
    __syncthreads();

    // LayerNorm over o (4 threads per row, shuffle reduce)
    {
        int q = tid & 3, r = tid >> 2;
        float s = 0.f, s2 = 0.f;
        for (int o = q; o < 128; o += 4) {
            float t = sh_y[r * 133 + o];
            s += t; s2 = fmaf(t, t, s2);
        }
        s  += __shfl_xor_sync(0xffffffffu, s, 1);
        s  += __shfl_xor_sync(0xffffffffu, s, 2);
        s2 += __shfl_xor_sync(0xffffffffu, s2, 1);
        s2 += __shfl_xor_sync(0xffffffffu, s2, 2);
        float m = s * 0.0078125f;
        float var = fmaf(-m, m, s2 * 0.0078125f);
        if (q == 0) { smean[r] = m; srstd[r] = rsqrtf(var + 1e-5f); }
    }
    __syncthreads();

    // normalize + write transposed to global (coalesced over r)
    {
        const float* gv = gamma + v * 128;
        const float* bv = beta + v * 128;
        float* dst = g_stackedT + ((size_t)blockIdx.x * 2048 + v * 128) * 64;
        for (int idx = tid; idx < 8192; idx += 256) {
            int r = idx & 63, o = idx >> 6;
            float val = fmaf((sh_y[r * 133 + o] - smean[r]) * srstd[r], gv[o], bv[o]);
            dst[o * 64 + r] = val;
        }
    }
}

// ---------------------------------------------------------------------------
// Stage 2: softmax GRN + weighted sum. grid = N/64, 256 threads.
// ---------------------------------------------------------------------------
__global__ void __launch_bounds__(256) vsn_stage2(
    const float* __restrict__ sW1, const float* __restrict__ sb1,
    const float* __restrict__ sW2, const float* __restrict__ sb2,
    const float* __restrict__ sWg, const float* __restrict__ sbg,
    const float* __restrict__ sWs, const float* __restrict__ sbs,
    const float* __restrict__ sgamma, const float* __restrict__ sbeta,
    float* __restrict__ outp, float* __restrict__ outw)
{
    extern __shared__ float sm[];
    float* sh_f  = sm;            // [128][64] flat chunk, k-major (matches global layout)
    float* warea = sm + 8192;     // 17024 floats, multi-use
    float* sh_ws = sm + 25216;    // [16][132]
    float* sh_sk = sm + 27328;    // [64][17]
    float* sh_z  = sm + 28416;    // [64][17]
    float* sh_w  = sm + 29504;    // [64][17]

    float* sh_w1 = warea;           // [128][133] during main GEMM
    float* sh_hs = warea;           // [64][133]  after GEMM
    float* sh_s2 = warea + 8512;    // [16][130]
    float* sh_sg = warea + 10592;   // [16][130]
    float* sh_o  = warea;           // [64][132]  pass-3 output staging

    const int tid = threadIdx.x;
    const int rt = tid & 15;        // rows rt*4 .. rt*4+3
    const int jt = tid >> 4;        // hs outputs jt*8 .. jt*8+7 ; sks output v=jt
    const int tile = blockIdx.x;
    const size_t rowbase = (size_t)tile * 64;
    const float* fbase = g_stackedT + (size_t)tile * 2048 * 64;

    float acc[32];
    float accs[4];
    #pragma unroll
    for (int i = 0; i < 32; i++) acc[i] = 0.f;
    accs[0] = accs[1] = accs[2] = accs[3] = 0.f;

    // ---- main GEMM: hs (64x128) and sks (64x16) over K=2048 in 16 chunks ----
    for (int c = 0; c < 16; c++) {
        __syncthreads();
        {   // flat chunk: identical layout -> raw float4 copy, conflict-free
            const float4* src = (const float4*)(fbase + (size_t)c * 128 * 64);
            float4* dst = (float4*)sh_f;
            for (int idx = tid; idx < 2048; idx += 256) dst[idx] = src[idx];
        }
        for (int idx = tid; idx < 4096; idx += 256) {
            int j = idx >> 5, kq = (idx & 31) * 4;
            float4 a = *(const float4*)(sW1 + (size_t)j * 2048 + c * 128 + kq);
            float* p = sh_w1 + j * 133 + kq;
            p[0] = a.x; p[1] = a.y; p[2] = a.z; p[3] = a.w;
        }
        for (int idx = tid; idx < 512; idx += 256) {
            int vv = idx >> 5, kq = (idx & 31) * 4;
            float4 a = *(const float4*)(sWs + (size_t)vv * 2048 + c * 128 + kq);
            float* p = sh_ws + vv * 132 + kq;
            p[0] = a.x; p[1] = a.y; p[2] = a.z; p[3] = a.w;
        }
        __syncthreads();

        #pragma unroll 8
        for (int kk = 0; kk < 128; kk++) {
            float4 fv = *(const float4*)(sh_f + kk * 64 + rt * 4);
            float wsv = sh_ws[jt * 132 + kk];
            accs[0] = fmaf(fv.x, wsv, accs[0]);
            accs[1] = fmaf(fv.y, wsv, accs[1]);
            accs[2] = fmaf(fv.z, wsv, accs[2]);
            accs[3] = fmaf(fv.w, wsv, accs[3]);
            #pragma unroll
            for (int i = 0; i < 8; i++) {
                float w = sh_w1[(jt * 8 + i) * 133 + kk];
                acc[0 * 8 + i] = fmaf(fv.x, w, acc[0 * 8 + i]);
                acc[1 * 8 + i] = fmaf(fv.y, w, acc[1 * 8 + i]);
                acc[2 * 8 + i] = fmaf(fv.z, w, acc[2 * 8 + i]);
                acc[3 * 8 + i] = fmaf(fv.w, w, acc[3 * 8 + i]);
            }
        }
    }
    __syncthreads();   // sh_w1 reads done; safe to overlay

    // sks -> shared, hs (elu) -> shared
    #pragma unroll
    for (int j = 0; j < 4; j++)
        sh_sk[(rt * 4 + j) * 17 + jt] = accs[j] + sbs[jt];
    #pragma unroll
    for (int i = 0; i < 8; i++) {
        int jj = jt * 8 + i;
        float bb = sb1[jj];
        #pragma unroll
        for (int j = 0; j < 4; j++)
            sh_hs[(rt * 4 + j) * 133 + jj] = eluf(acc[j * 8 + i] + bb);
    }
    // stage sW2/sWg (16x128 each)
    for (int idx = tid; idx < 512; idx += 256) {
        int vv = idx >> 5, jq = (idx & 31) * 4;
        float4 a = *(const float4*)(sW2 + vv * 128 + jq);
        float* p = sh_s2 + vv * 130 + jq;
        p[0] = a.x; p[1] = a.y; p[2] = a.z; p[3] = a.w;
        float4 b = *(const float4*)(sWg + vv * 128 + jq);
        float* q = sh_sg + vv * 130 + jq;
        q[0] = b.x; q[1] = b.y; q[2] = b.z; q[3] = b.w;
    }
    __syncthreads();

    // tiny GEMM 128 -> 16 (x2) and GRN combine: thread = (row, quarter of v's)
    {
        int q = tid & 3, r = tid >> 2;
        float a2[4] = {0.f, 0.f, 0.f, 0.f};
        float ag[4] = {0.f, 0.f, 0.f, 0.f};
        #pragma unroll 4
        for (int j = 0; j < 128; j++) {
            float hsv = sh_hs[r * 133 + j];
            #pragma unroll
            for (int i = 0; i < 4; i++) {
                a2[i] = fmaf(hsv, sh_s2[(q * 4 + i) * 130 + j], a2[i]);
                ag[i] = fmaf(hsv, sh_sg[(q * 4 + i) * 130 + j], ag[i]);
            }
        }
        #pragma unroll
        for (int i = 0; i < 4; i++) {
            int vv = q * 4 + i;
            float h2s = a2[i] + sb2[vv];
            float gs = sigm(ag[i] + sbg[vv]);
            float sk = sh_sk[r * 17 + vv];
            sh_z[r * 17 + vv] = gs * h2s + (1.f - gs) * sk;
        }
    }
    __syncthreads();

    // LN over 16 + softmax, one thread per row
    if (tid < 64) {
        float zz[16];
        float s = 0.f;
        #pragma unroll
        for (int vv = 0; vv < 16; vv++) { zz[vv] = sh_z[tid * 17 + vv]; s += zz[vv]; }
        float m = s * 0.0625f;
        float s2 = 0.f;
        #pragma unroll
        for (int vv = 0; vv < 16; vv++) { float d = zz[vv] - m; s2 = fmaf(d, d, s2); }
        float rstd = rsqrtf(s2 * 0.0625f + 1e-5f);
        float mx = -3.4e38f;
        #pragma unroll
        for (int vv = 0; vv < 16; vv++) {
            zz[vv] = fmaf((zz[vv] - m) * rstd, sgamma[vv], sbeta[vv]);
            mx = fmaxf(mx, zz[vv]);
        }
        float se = 0.f;
        #pragma unroll
        for (int vv = 0; vv < 16; vv++) { zz[vv] = expf(zz[vv] - mx); se += zz[vv]; }
        float inv = 1.f / se;
        #pragma unroll
        for (int vv = 0; vv < 16; vv++) sh_w[tid * 17 + vv] = zz[vv] * inv;
    }
    __syncthreads();

    // weights out (coalesced)
    for (int idx = tid; idx < 1024; idx += 256) {
        int r = idx >> 4, vv = idx & 15;
        outw[(rowbase + r) * 16 + vv] = sh_w[r * 17 + vv];
    }

    // ---- pass 3: processed[r][d] = sum_v stacked[r][v][d] * w[r][v] ----
    float accp[32];
    #pragma unroll
    for (int i = 0; i < 32; i++) accp[i] = 0.f;

    for (int vv = 0; vv < 16; vv++) {
        __syncthreads();
        {
            const float4* src = (const float4*)(fbase + (size_t)vv * 128 * 64);
            float4* dst = (float4*)sh_f;
            for (int idx = tid; idx < 2048; idx += 256) dst[idx] = src[idx];
        }
        __syncthreads();
        float wv0 = sh_w[(rt * 4 + 0) * 17 + vv];
        float wv1 = sh_w[(rt * 4 + 1) * 17 + vv];
        float wv2 = sh_w[(rt * 4 + 2) * 17 + vv];
        float wv3 = sh_w[(rt * 4 + 3) * 17 + vv];
        #pragma unroll
        for (int dd = 0; dd < 8; dd++) {
            float4 fv = *(const float4*)(sh_f + (jt * 8 + dd) * 64 + rt * 4);
            accp[0 * 8 + dd] = fmaf(fv.x, wv0, accp[0 * 8 + dd]);
            accp[1 * 8 + dd] = fmaf(fv.y, wv1, accp[1 * 8 + dd]);
            accp[2 * 8 + dd] = fmaf(fv.z, wv2, accp[2 * 8 + dd]);
            accp[3 * 8 + dd] = fmaf(fv.w, wv3, accp[3 * 8 + dd]);
        }
    }
    __syncthreads();
    #pragma unroll
    for (int j = 0; j < 4; j++) {
        #pragma unroll
        for (int dd = 0; dd < 8; dd++)
            sh_o[(rt * 4 + j) * 132 + jt * 8 + dd] = accp[j * 8 + dd];
    }
    __syncthreads();
    for (int idx = tid; idx < 2048; idx += 256) {
        int r = idx >> 5, dq = (idx & 31) * 4;
        float4 a = *(const float4*)(sh_o + r * 132 + dq);
        *(float4*)(outp + (rowbase + r) * 128 + dq) = a;
    }
}

// ---------------------------------------------------------------------------
extern "C" void kernel_launch(void* const* d_in, const int* in_sizes, int n_in,
                              void* d_out, int out_size) {
    const float* x      = (const float*)d_in[0];
    const float* W1     = (const float*)d_in[1];
    const float* b1     = (const float*)d_in[2];
    const float* W2     = (const float*)d_in[3];
    const float* b2     = (const float*)d_in[4];
    const float* Wg     = (const float*)d_in[5];
    const float* bg     = (const float*)d_in[6];
    const float* Ws     = (const float*)d_in[7];
    const float* bs     = (const float*)d_in[8];
    const float* gamma  = (const float*)d_in[9];
    const float* beta   = (const float*)d_in[10];
    const float* sW1    = (const float*)d_in[11];
    const float* sb1    = (const float*)d_in[12];
    const float* sW2    = (const float*)d_in[13];
    const float* sb2    = (const float*)d_in[14];
    const float* sWg    = (const float*)d_in[15];
    const float* sbg    = (const float*)d_in[16];
    const float* sWs    = (const float*)d_in[17];
    const float* sbs    = (const float*)d_in[18];
    const float* sgamma = (const float*)d_in[19];
    const float* sbeta  = (const float*)d_in[20];

    int N = in_sizes[0] / 16;          // 16384 rows
    int tiles = N / 64;                // 256

    float* outp = (float*)d_out;
    float* outw = outp + (size_t)N * 128;

    cudaFuncSetAttribute(vsn_stage1, cudaFuncAttributeMaxDynamicSharedMemorySize, 137216);
    cudaFuncSetAttribute(vsn_stage2, cudaFuncAttributeMaxDynamicSharedMemorySize, 122368);

    dim3 g1(tiles, 16);
    vsn_stage1<<<g1, 256, 137216>>>(x, W1, b1, W2, b2, Wg, bg, Ws, bs, gamma, beta);
    vsn_stage2<<<tiles, 256, 122368>>>(sW1, sb1, sW2, sb2, sWg, sbg, sWs, sbs,
                                       sgamma, sbeta, outp, outw);
}